// round 5
// baseline (speedup 1.0000x reference)
#include <cuda_runtime.h>
#include <math.h>

#define N_OBJ  16384
#define N_PAIR 131072
#define DD     256

// ---------------- scratch (static device memory; no allocations) ----------------
__device__ float g_objA[(size_t)N_OBJ  * DD];   // x_obj after step 0
__device__ float g_predA[(size_t)N_PAIR * DD];  // x_pred after step 0
__device__ float g_msgO[(size_t)N_OBJ  * DD];   // segment-sum target
__device__ float g_msgP[(size_t)N_PAIR * DD];   // m_s2p + m_o2p
__device__ float g_aO1[N_OBJ];   // relu(x_obj) . w_e2v[:D]
__device__ float g_aO2[N_OBJ];   // relu(x_obj) . w_v2e[D:]
__device__ float g_pP1[N_PAIR];  // relu(x_pred) . w_e2v[D:]
__device__ float g_pP2[N_PAIR];  // relu(x_pred) . w_v2e[:D]

__device__ __forceinline__ float sigf(float x) { return 1.0f / (1.0f + expf(-x)); }

// ---------------- per-row gate scalars: dot(relu(row), wA), dot(relu(row), wB) ----
__global__ void row_scalars(const float* __restrict__ X, int M,
                            const float* __restrict__ wA, const float* __restrict__ wB,
                            float* __restrict__ outA, float* __restrict__ outB)
{
    int warp = (blockIdx.x * blockDim.x + threadIdx.x) >> 5;
    int lane = threadIdx.x & 31;
    if (warp >= M) return;
    const float4* xr = (const float4*)(X + (size_t)warp * DD);
    const float4* wa4 = (const float4*)wA;
    const float4* wb4 = (const float4*)wB;
    float sA = 0.f, sB = 0.f;
#pragma unroll
    for (int h = 0; h < 2; ++h) {
        int c4 = lane + h * 32;              // 0..63 float4 chunks = 256 floats
        float4 v = xr[c4];
        float4 a = wa4[c4];
        float4 b = wb4[c4];
        float rx = fmaxf(v.x, 0.f), ry = fmaxf(v.y, 0.f);
        float rz = fmaxf(v.z, 0.f), rw = fmaxf(v.w, 0.f);
        sA += rx * a.x + ry * a.y + rz * a.z + rw * a.w;
        sB += rx * b.x + ry * b.y + rz * b.z + rw * b.w;
    }
#pragma unroll
    for (int o = 16; o > 0; o >>= 1) {
        sA += __shfl_xor_sync(0xFFFFFFFFu, sA, o);
        sB += __shfl_xor_sync(0xFFFFFFFFu, sB, o);
    }
    if (lane == 0) { outA[warp] = sA; outB[warp] = sB; }
}

// ---------------- zero msgO ----------------
__global__ void zero_kernel(float4* __restrict__ p, int n4)
{
    int i = blockIdx.x * blockDim.x + threadIdx.x;
    if (i < n4) p[i] = make_float4(0.f, 0.f, 0.f, 0.f);
}

// ---------------- edge kernel: scatter msgO (atomic), build msgP ----------------
__global__ void edge_kernel(const float* __restrict__ xp,   // x_pred  [N_PAIR][D]
                            const float* __restrict__ xo,   // x_obj   [N_OBJ][D]
                            const int*   __restrict__ pidx, // [N_PAIR][2]
                            const float* __restrict__ aO1, const float* __restrict__ aO2,
                            const float* __restrict__ pP1, const float* __restrict__ pP2,
                            const float* __restrict__ b_e2v, const float* __restrict__ b_v2e,
                            float* __restrict__ msgO, float* __restrict__ msgP)
{
    int e = (blockIdx.x * blockDim.x + threadIdx.x) >> 5;
    int lane = threadIdx.x & 31;
    if (e >= N_PAIR) return;

    int s = pidx[2 * e];
    int o = pidx[2 * e + 1];
    float be = b_e2v[0];
    float bv = b_v2e[0];
    float p1 = pP1[e], p2 = pP2[e];
    float g1 = sigf(aO1[s] + p1 + be);   // m_subj = g1 * x_pred[e]  -> msgO[s]
    float g2 = sigf(aO1[o] + p1 + be);   // m_obj  = g2 * x_pred[e]  -> msgO[o]
    float gs = sigf(aO2[s] + p2 + bv);   // m_s2p  = gs * x_obj[s]
    float go = sigf(aO2[o] + p2 + bv);   // m_o2p  = go * x_obj[o]

    const float4* xpr = (const float4*)(xp + (size_t)e * DD);
    const float4* xsr = (const float4*)(xo + (size_t)s * DD);
    const float4* xor4 = (const float4*)(xo + (size_t)o * DD);
    float4* mp  = (float4*)(msgP + (size_t)e * DD);
    float4* mos = (float4*)(msgO + (size_t)s * DD);
    float4* moo = (float4*)(msgO + (size_t)o * DD);

#pragma unroll
    for (int h = 0; h < 2; ++h) {
        int c = lane + h * 32;
        float4 vp = xpr[c];
        float4 vs = xsr[c];
        float4 vo = xor4[c];

        float4 outp;
        outp.x = gs * vs.x + go * vo.x;
        outp.y = gs * vs.y + go * vo.y;
        outp.z = gs * vs.z + go * vo.z;
        outp.w = gs * vs.w + go * vo.w;
        mp[c] = outp;

        float4 as = make_float4(g1 * vp.x, g1 * vp.y, g1 * vp.z, g1 * vp.w);
        float4 ao = make_float4(g2 * vp.x, g2 * vp.y, g2 * vp.z, g2 * vp.w);
        atomicAdd(&mos[c], as);   // vectorized float4 red (sm_90+), L2-resident target
        atomicAdd(&moo[c], ao);
    }
}

// ---------------- fused 6-way GEMM + GRU elementwise ----------------
// Y = GRU(X, H): gi = X @ Wih^T + bih ; gh = H @ Whh^T + bhh ; standard GRU cell.
// Block tile: BM=64 rows, BN=32 output cols, BK=32. 6 accumulator tiles
// (3 gates x {ih, hh}). 256 threads; each thread owns 4(m) x 2(n) x 6 accums.
#define BM 64
#define BN 32
#define BK 32

__global__ __launch_bounds__(256, 2)
void gru_kernel(const float* __restrict__ X, const float* __restrict__ H,
                const float* __restrict__ Wih, const float* __restrict__ Whh,
                const float* __restrict__ bih, const float* __restrict__ bhh,
                float* __restrict__ Y, int M)
{
    __shared__ __align__(16) float AsX[BK][BM + 4];
    __shared__ __align__(16) float AsH[BK][BM + 4];
    __shared__ __align__(16) float Bs[6][BK][BN + 2];

    const int bn = blockIdx.x;           // output-col block (0..7), d0 = bn*32
    const int bm = blockIdx.y;           // row block
    const int m0 = bm * BM;
    const int d0 = bn * BN;
    const int tid = threadIdx.x;
    const int tm = tid & 15;             // micro-tile m group (4 rows)
    const int tn = tid >> 4;             // micro-tile n group (2 cols)

    float accX[3][4][2] = {};
    float accH[3][4][2] = {};
    float hval[4][2];

    const int arow = tid >> 3;           // 0..31
    const int ac4  = tid & 7;            // 0..7 float4 chunk within BK

#pragma unroll 1
    for (int kc = 0; kc < DD / BK; ++kc) {
        const int k0 = kc * BK;
        // -------- stage A tiles (X and H), transposed to [k][m] --------
#pragma unroll
        for (int rr = 0; rr < 2; ++rr) {
            int r = arow + rr * 32;
            float4 vx = *(const float4*)(X + (size_t)(m0 + r) * DD + k0 + ac4 * 4);
            float4 vh = *(const float4*)(H + (size_t)(m0 + r) * DD + k0 + ac4 * 4);
            AsX[ac4 * 4 + 0][r] = vx.x; AsX[ac4 * 4 + 1][r] = vx.y;
            AsX[ac4 * 4 + 2][r] = vx.z; AsX[ac4 * 4 + 3][r] = vx.w;
            AsH[ac4 * 4 + 0][r] = vh.x; AsH[ac4 * 4 + 1][r] = vh.y;
            AsH[ac4 * 4 + 2][r] = vh.z; AsH[ac4 * 4 + 3][r] = vh.w;
        }
        // -------- stage 6 B tiles, transposed to [k][n] --------
#pragma unroll
        for (int g = 0; g < 6; ++g) {
            const float* W = (g < 3) ? Wih : Whh;
            int grow = (g % 3) * DD + d0 + arow;       // weight row (output col)
            float4 v = *(const float4*)(W + (size_t)grow * DD + k0 + ac4 * 4);
            Bs[g][ac4 * 4 + 0][arow] = v.x; Bs[g][ac4 * 4 + 1][arow] = v.y;
            Bs[g][ac4 * 4 + 2][arow] = v.z; Bs[g][ac4 * 4 + 3][arow] = v.w;
        }
        __syncthreads();

        if (kc == bn) {
            // H[m][d] for the z*h blend: d-cols of this block == k-cols of chunk bn
#pragma unroll
            for (int i = 0; i < 4; ++i)
#pragma unroll
                for (int j = 0; j < 2; ++j)
                    hval[i][j] = AsH[tn * 2 + j][tm * 4 + i];
        }

#pragma unroll
        for (int kk = 0; kk < BK; ++kk) {
            float4 ax = *(const float4*)&AsX[kk][tm * 4];
            float4 ah = *(const float4*)&AsH[kk][tm * 4];
            float2 b[6];
#pragma unroll
            for (int g = 0; g < 6; ++g)
                b[g] = *(const float2*)&Bs[g][kk][tn * 2];
            float am[4] = {ax.x, ax.y, ax.z, ax.w};
            float hm[4] = {ah.x, ah.y, ah.z, ah.w};
#pragma unroll
            for (int g = 0; g < 3; ++g)
#pragma unroll
                for (int i = 0; i < 4; ++i) {
                    accX[g][i][0] += am[i] * b[g].x;
                    accX[g][i][1] += am[i] * b[g].y;
                    accH[g][i][0] += hm[i] * b[g + 3].x;
                    accH[g][i][1] += hm[i] * b[g + 3].y;
                }
        }
        __syncthreads();
    }

    // -------- epilogue: GRU elementwise --------
#pragma unroll
    for (int i = 0; i < 4; ++i) {
        int m = m0 + tm * 4 + i;
        float ov[2];
#pragma unroll
        for (int j = 0; j < 2; ++j) {
            int d = d0 + tn * 2 + j;
            float ir = accX[0][i][j] + bih[d];
            float iz = accX[1][i][j] + bih[DD + d];
            float in_ = accX[2][i][j] + bih[2 * DD + d];
            float hr = accH[0][i][j] + bhh[d];
            float hz = accH[1][i][j] + bhh[DD + d];
            float hn = accH[2][i][j] + bhh[2 * DD + d];
            float r = sigf(ir + hr);
            float z = sigf(iz + hz);
            float n = tanhf(in_ + r * hn);
            ov[j] = (1.0f - z) * n + z * hval[i][j];
        }
        float2 o2 = make_float2(ov[0], ov[1]);
        *(float2*)(Y + (size_t)m * DD + d0 + tn * 2) = o2;
    }
}

// ---------------- driver ----------------
static void run_step(const float* cur_obj, const float* cur_pred,
                     float* next_obj, float* next_pred,
                     const int* pidx,
                     const float* w_e2v, const float* b_e2v,
                     const float* w_v2e, const float* b_v2e,
                     const float* w_ih, const float* w_hh,
                     const float* b_ih, const float* b_hh,
                     float* aO1, float* aO2, float* pP1, float* pP2,
                     float* msgO, float* msgP)
{
    // node gate scalars: aO1 = relu(x_obj).w_e2v[:D], aO2 = relu(x_obj).w_v2e[D:]
    row_scalars<<<(N_OBJ * 32 + 255) / 256, 256>>>(cur_obj, N_OBJ, w_e2v, w_v2e + DD, aO1, aO2);
    // edge gate scalars: pP1 = relu(x_pred).w_e2v[D:], pP2 = relu(x_pred).w_v2e[:D]
    row_scalars<<<(N_PAIR * 32 + 255) / 256, 256>>>(cur_pred, N_PAIR, w_e2v + DD, w_v2e, pP1, pP2);
    // clear segment-sum target
    zero_kernel<<<(N_OBJ * DD / 4 + 255) / 256, 256>>>((float4*)msgO, N_OBJ * DD / 4);
    // gates + scatter + pred message build
    edge_kernel<<<(N_PAIR * 32 + 255) / 256, 256>>>(cur_pred, cur_obj, pidx,
                                                    aO1, aO2, pP1, pP2,
                                                    b_e2v, b_v2e, msgO, msgP);
    // GRU updates
    gru_kernel<<<dim3(DD / BN, N_OBJ / BM), 256>>>(msgO, cur_obj, w_ih, w_hh, b_ih, b_hh,
                                                   next_obj, N_OBJ);
    gru_kernel<<<dim3(DD / BN, N_PAIR / BM), 256>>>(msgP, cur_pred, w_ih, w_hh, b_ih, b_hh,
                                                    next_pred, N_PAIR);
}

extern "C" void kernel_launch(void* const* d_in, const int* in_sizes, int n_in,
                              void* d_out, int out_size)
{
    (void)in_sizes; (void)n_in; (void)out_size;
    const float* x_obj  = (const float*)d_in[0];
    const float* x_pred = (const float*)d_in[1];
    const int*   pidx   = (const int*)d_in[2];
    const float* w_e2v  = (const float*)d_in[3];
    const float* b_e2v  = (const float*)d_in[4];
    const float* w_v2e  = (const float*)d_in[5];
    const float* b_v2e  = (const float*)d_in[6];
    const float* w_ih   = (const float*)d_in[7];
    const float* w_hh   = (const float*)d_in[8];
    const float* b_ih   = (const float*)d_in[9];
    const float* b_hh   = (const float*)d_in[10];
    float* out = (float*)d_out;

    float *objA, *predA, *msgO, *msgP, *aO1, *aO2, *pP1, *pP2;
    cudaGetSymbolAddress((void**)&objA,  g_objA);
    cudaGetSymbolAddress((void**)&predA, g_predA);
    cudaGetSymbolAddress((void**)&msgO,  g_msgO);
    cudaGetSymbolAddress((void**)&msgP,  g_msgP);
    cudaGetSymbolAddress((void**)&aO1,   g_aO1);
    cudaGetSymbolAddress((void**)&aO2,   g_aO2);
    cudaGetSymbolAddress((void**)&pP1,   g_pP1);
    cudaGetSymbolAddress((void**)&pP2,   g_pP2);

    float* out_obj  = out;
    float* out_pred = out + (size_t)N_OBJ * DD;

    // step 0: inputs -> scratch
    run_step(x_obj, x_pred, objA, predA, pidx,
             w_e2v, b_e2v, w_v2e, b_v2e, w_ih, w_hh, b_ih, b_hh,
             aO1, aO2, pP1, pP2, msgO, msgP);
    // step 1: scratch -> output
    run_step(objA, predA, out_obj, out_pred, pidx,
             w_e2v, b_e2v, w_v2e, b_v2e, w_ih, w_hh, b_ih, b_hh,
             aO1, aO2, pP1, pP2, msgO, msgP);
}